// round 13
// baseline (speedup 1.0000x reference)
#include <cuda_runtime.h>
#include <cuda_bf16.h>
#include <stdint.h>
#include <math.h>

#define BATCH 2
#define CH    256
#define HH    96
#define WW    96
#define HW    (HH*WW)        // 9216
#define OUTC  256
#define KTAPS 9
#define KDIM  (KTAPS*CH)     // 2304
#define MROWS (BATCH*HW)     // 18432
#define NOFF  32             // 27 padded to 32

#define SW128(o) ((o) ^ ((((o) >> 3) & 0x70)))

struct __align__(16) SInfo { int i0,i1,i2,i3; float w0,w1,w2,w3; };

// ---- scratch (device globals: allocation-free) ----
__device__ float g_xT [MROWS*CH];        // x NHWC fp32
__device__ float g_h1T[MROWS*CH];        // layer-1 out NHWC fp32
__device__ float g_h2T[MROWS*CH];        // layer-2 out NHWC fp32
__device__ SInfo g_sinfo[MROWS*KTAPS];   // bilinear indices+weights
// main weights in mma-B-fragment order, bf16 hi/lo:
//   [layer][blk36 = tap*4+g][kb4][nb32][lane32] uint2{pack(k0,k1), pack(k0+8,k1+8)}
__device__ uint2 g_bwmh[2*36*4096];
__device__ uint2 g_bwml[2*36*4096];
// offset weights, same frag order, N=32: [layer][blk36][kb4][nb4][lane32]
__device__ uint2 g_bwoh[2*36*512];
__device__ uint2 g_bwol[2*36*512];

// ====================== helpers ======================
__device__ __forceinline__ uint32_t smem_u32(const void* p) {
    uint32_t a;
    asm("{ .reg .u64 t; cvta.to.shared.u64 t, %1; cvt.u32.u64 %0, t; }" : "=r"(a) : "l"(p));
    return a;
}

__device__ __forceinline__ void split_bf16(float v, uint16_t& h, uint16_t& l) {
    __nv_bfloat16 hb = __float2bfloat16_rn(v);
    float lo = v - __bfloat162float(hb);
    __nv_bfloat16 lb = __float2bfloat16_rn(lo);
    h = __bfloat16_as_ushort(hb);
    l = __bfloat16_as_ushort(lb);
}

#define LDSM4(r0,r1,r2,r3, addr)                                                    \
    asm volatile("ldmatrix.sync.aligned.m8n8.x4.shared.b16 {%0,%1,%2,%3}, [%4];"    \
        : "=r"(r0), "=r"(r1), "=r"(r2), "=r"(r3) : "r"(addr))

#define MMA16816(d, a0,a1,a2,a3, b0,b1)                                             \
    asm volatile("mma.sync.aligned.m16n8k16.row.col.f32.bf16.bf16.f32 "             \
        "{%0,%1,%2,%3}, {%4,%5,%6,%7}, {%8,%9}, {%0,%1,%2,%3};"                     \
        : "+f"((d)[0]), "+f"((d)[1]), "+f"((d)[2]), "+f"((d)[3])                    \
        : "r"(a0), "r"(a1), "r"(a2), "r"(a3), "r"(b0), "r"(b1))

#define CP_ASYNC16(dst, src) \
    asm volatile("cp.async.cg.shared.global [%0], [%1], 16;" :: "r"(dst), "l"(src))
#define CP_COMMIT() asm volatile("cp.async.commit_group;" ::: "memory")
#define CP_WAIT0()  asm volatile("cp.async.wait_group 0;" ::: "memory")

// ====================== weight prep ======================
__global__ void prep_main_mma(const float* __restrict__ w, int layer) {
    int idx = blockIdx.x*256 + threadIdx.x;           // 36*4096 = 147456
    if (idx >= 36*4096) return;
    int lane = idx & 31;
    int nb   = (idx >> 5) & 31;
    int kb   = (idx >> 10) & 3;
    int blk  = idx >> 12;
    int tap  = blk >> 2, g = blk & 3;
    int n    = nb*8 + (lane >> 2);
    int c0   = g*64 + kb*16 + (lane & 3)*2;
    const float* wb = w + (size_t)n*CH*KTAPS + tap;
    float v00 = wb[(size_t)(c0    )*KTAPS];
    float v01 = wb[(size_t)(c0 + 1)*KTAPS];
    float v10 = wb[(size_t)(c0 + 8)*KTAPS];
    float v11 = wb[(size_t)(c0 + 9)*KTAPS];
    uint16_t h00,l00,h01,l01,h10,l10,h11,l11;
    split_bf16(v00,h00,l00); split_bf16(v01,h01,l01);
    split_bf16(v10,h10,l10); split_bf16(v11,h11,l11);
    size_t o = (size_t)layer*36*4096 + idx;
    g_bwmh[o] = make_uint2((uint32_t)h00 | ((uint32_t)h01 << 16),
                           (uint32_t)h10 | ((uint32_t)h11 << 16));
    g_bwml[o] = make_uint2((uint32_t)l00 | ((uint32_t)l01 << 16),
                           (uint32_t)l10 | ((uint32_t)l11 << 16));
}

__global__ void prep_off_mma(const float* __restrict__ woff, int layer) {
    int idx = blockIdx.x*256 + threadIdx.x;           // 36*512 = 18432
    if (idx >= 36*512) return;
    int lane = idx & 31;
    int nb   = (idx >> 5) & 3;
    int kb   = (idx >> 7) & 3;
    int blk  = idx >> 9;
    int tap  = blk >> 2, g = blk & 3;
    int n    = nb*8 + (lane >> 2);
    int c0   = g*64 + kb*16 + (lane & 3)*2;
    float v00 = 0.f, v01 = 0.f, v10 = 0.f, v11 = 0.f;
    if (n < 27) {
        const float* wb = woff + (size_t)n*CH*KTAPS + tap;
        v00 = wb[(size_t)(c0    )*KTAPS];
        v01 = wb[(size_t)(c0 + 1)*KTAPS];
        v10 = wb[(size_t)(c0 + 8)*KTAPS];
        v11 = wb[(size_t)(c0 + 9)*KTAPS];
    }
    uint16_t h00,l00,h01,l01,h10,l10,h11,l11;
    split_bf16(v00,h00,l00); split_bf16(v01,h01,l01);
    split_bf16(v10,h10,l10); split_bf16(v11,h11,l11);
    size_t o = (size_t)layer*36*512 + idx;
    g_bwoh[o] = make_uint2((uint32_t)h00 | ((uint32_t)h01 << 16),
                           (uint32_t)h10 | ((uint32_t)h11 << 16));
    g_bwol[o] = make_uint2((uint32_t)l00 | ((uint32_t)l01 << 16),
                           (uint32_t)l10 | ((uint32_t)l11 << 16));
}

// ====================== layout transposes ======================
__global__ void nchw_to_nhwc_k(const float* __restrict__ src) {
    __shared__ float t[32][33];
    int b  = blockIdx.z;
    int p0 = blockIdx.x*32, c0 = blockIdx.y*32;
    int tx = threadIdx.x,  ty = threadIdx.y;
    #pragma unroll
    for (int i = 0; i < 32; i += 8)
        t[ty+i][tx] = src[(size_t)(b*CH + c0+ty+i)*HW + p0 + tx];
    __syncthreads();
    #pragma unroll
    for (int i = 0; i < 32; i += 8)
        g_xT[(size_t)(b*HW + p0+ty+i)*CH + c0 + tx] = t[tx][ty+i];
}

__global__ void nhwc_to_nchw_k(float* __restrict__ dst) {
    __shared__ float t[32][33];
    int b  = blockIdx.z;
    int p0 = blockIdx.x*32, c0 = blockIdx.y*32;
    int tx = threadIdx.x,  ty = threadIdx.y;
    #pragma unroll
    for (int i = 0; i < 32; i += 8)
        t[ty+i][tx] = g_h2T[(size_t)(b*HW + p0+ty+i)*CH + c0 + tx];
    __syncthreads();
    #pragma unroll
    for (int i = 0; i < 32; i += 8)
        dst[(size_t)(b*CH + c0+ty+i)*HW + p0 + tx] = t[tx][ty+i];
}

// ====================== offset conv (mma bf16x3, N=32, BM=64) + fused coords ======================
#define OA_H 0
#define OA_L 8192
#define OB_H 16384
#define OB_L 20480
#define OM_S 24576
#define OFF_SMEM (24576 + 8192 + 1024)

__launch_bounds__(256, 2)
__global__ void gemm_off_mma(int layer, const float* __restrict__ bias) {
    extern __shared__ unsigned char dsm[];
    uint32_t raw = smem_u32(dsm);
    uint32_t sb  = (raw + 1023u) & ~1023u;
    unsigned char* smp = dsm + (sb - raw);

    int tid = threadIdx.x, wid = tid >> 5, lane = tid & 31;
    int wm  = wid & 3, wn = wid >> 2;
    int bm  = blockIdx.x;                   // 288 tiles of 64 px
    const float* in = layer ? g_h1T : g_xT;
    const uint2* bwh = g_bwoh + (size_t)layer*36*512;
    const uint2* bwl = g_bwol + (size_t)layer*36*512;

    int c4 = tid & 15;                      // 4-ch quad within 64-ch group
    int pg = tid >> 4;                      // 4-px group
    int b  = (bm*64) / HW;
    int pbase = bm*64 - b*HW;
    const float* inb = in + (size_t)b*HW*CH;

    float acc[2][4];
    #pragma unroll
    for (int i = 0; i < 2; i++)
        #pragma unroll
        for (int j = 0; j < 4; j++) acc[i][j] = 0.0f;

    uint32_t a_rel = (uint32_t)((wm*16 + (lane & 15))*128 + (lane >> 4)*16);

    for (int g = 0; g < 4; g++) {
        #pragma unroll 1
        for (int tap = 0; tap < 9; tap++) {
            int blk = tap*4 + g;
            int cc  = g*64 + c4*4;
            int dy  = tap/3 - 1, dx = tap%3 - 1;
            float4 av[4];
            #pragma unroll
            for (int i = 0; i < 4; i++) {
                int px = pg*4 + i;
                int p  = pbase + px;
                int y  = p / WW, x = p - y*WW;
                int ny = y + dy, nx = x + dx;
                bool valid = ((unsigned)ny < HH) & ((unsigned)nx < WW);
                av[i] = valid ? *(const float4*)(inb + (size_t)(ny*WW + nx)*CH + cc)
                              : make_float4(0.f,0.f,0.f,0.f);
            }
            __syncthreads();
            CP_ASYNC16(sb + OB_H + tid*16, (const void*)((const uint4*)(bwh + (size_t)blk*512) + tid));
            CP_ASYNC16(sb + OB_L + tid*16, (const void*)((const uint4*)(bwl + (size_t)blk*512) + tid));
            CP_COMMIT();
            #pragma unroll
            for (int i = 0; i < 4; i++) {
                int px = pg*4 + i;
                uint16_t h0,l0,h1,l1,h2,l2,h3,l3;
                split_bf16(av[i].x,h0,l0); split_bf16(av[i].y,h1,l1);
                split_bf16(av[i].z,h2,l2); split_bf16(av[i].w,h3,l3);
                uint32_t so = SW128((uint32_t)(px*128 + c4*8));
                *(uint2*)(smp + OA_H + so) =
                    make_uint2((uint32_t)h0 | ((uint32_t)h1 << 16),
                               (uint32_t)h2 | ((uint32_t)h3 << 16));
                *(uint2*)(smp + OA_L + so) =
                    make_uint2((uint32_t)l0 | ((uint32_t)l1 << 16),
                               (uint32_t)l2 | ((uint32_t)l3 << 16));
            }
            CP_WAIT0();
            __syncthreads();

            #pragma unroll
            for (int kb = 0; kb < 4; kb++) {
                uint32_t aoff = SW128(a_rel + (uint32_t)(kb*32));
                uint32_t ah0,ah1,ah2,ah3, al0,al1,al2,al3;
                LDSM4(ah0,ah1,ah2,ah3, sb + OA_H + aoff);
                LDSM4(al0,al1,al2,al3, sb + OA_L + aoff);
                #pragma unroll
                for (int j = 0; j < 2; j++) {
                    int nb = wn*2 + j;
                    uint32_t boff = (uint32_t)(((kb*4 + nb)*32 + lane)*8);
                    uint2 bh = *(const uint2*)(smp + OB_H + boff);
                    uint2 bl = *(const uint2*)(smp + OB_L + boff);
                    MMA16816(acc[j], ah0,ah1,ah2,ah3, bh.x, bh.y);
                    MMA16816(acc[j], al0,al1,al2,al3, bh.x, bh.y);
                    MMA16816(acc[j], ah0,ah1,ah2,ah3, bl.x, bl.y);
                }
            }
        }
    }

    // ---- fused epilogue: om -> smem, then coords -> g_sinfo ----
    float* om_s = (float*)(smp + OM_S);
    int crow = lane >> 2, ccol = (lane & 3)*2;
    int prow = wm*16 + crow;
    #pragma unroll
    for (int j = 0; j < 2; j++) {
        int col = (wn*2 + j)*8 + ccol;
        float bv0 = (col     < 27) ? __ldg(bias + col)     : 0.0f;
        float bv1 = (col + 1 < 27) ? __ldg(bias + col + 1) : 0.0f;
        om_s[prow*32 + col]       = acc[j][0] + bv0;
        om_s[prow*32 + col + 1]   = acc[j][1] + bv1;
        om_s[(prow+8)*32 + col]   = acc[j][2] + bv0;
        om_s[(prow+8)*32 + col+1] = acc[j][3] + bv1;
    }
    __syncthreads();

    #pragma unroll
    for (int t = 0; t < 3; t++) {
        int i = tid + t*256;
        if (i < 64*KTAPS) {
            int px  = i / 9;
            int tap = i - px*9;
            int gp  = bm*64 + px;
            int p   = gp - b*HW;
            int y   = p / WW, x = p - y*WW;
            const float* om = om_s + px*32;
            float ody = om[2*tap], odx = om[2*tap + 1];
            float m   = 1.0f / (1.0f + expf(-om[18 + tap]));
            float ys = (float)(y + tap/3 - 1) + ody;
            float xs = (float)(x + tap%3 - 1) + odx;
            float fy0 = floorf(ys), fx0 = floorf(xs);
            int y0 = (int)fy0, x0 = (int)fx0;
            int y1 = y0 + 1,   x1 = x0 + 1;
            float wy1 = ys - fy0, wx1 = xs - fx0;
            float wy0 = 1.0f - wy1, wx0 = 1.0f - wx1;
            int y0c = min(max(y0,0),HH-1), y1c = min(max(y1,0),HH-1);
            int x0c = min(max(x0,0),WW-1), x1c = min(max(x1,0),WW-1);
            float vy0 = ((unsigned)y0 < HH) ? 1.0f : 0.0f;
            float vy1 = ((unsigned)y1 < HH) ? 1.0f : 0.0f;
            float vx0 = ((unsigned)x0 < WW) ? 1.0f : 0.0f;
            float vx1 = ((unsigned)x1 < WW) ? 1.0f : 0.0f;
            SInfo s;
            s.i0 = y0c*WW + x0c;  s.w0 = wy0*wx0*m*vy0*vx0;
            s.i1 = y0c*WW + x1c;  s.w1 = wy0*wx1*m*vy0*vx1;
            s.i2 = y1c*WW + x0c;  s.w2 = wy1*wx0*m*vy1*vx0;
            s.i3 = y1c*WW + x1c;  s.w3 = wy1*wx1*m*vy1*vx1;
            g_sinfo[(size_t)gp*KTAPS + tap] = s;
        }
    }
}

// ====================== main deformable conv: mma bf16x3, BM=128 BN=256 ======================
// 8 warps, warp tile 64x64. 3 A-buffers (32KB each: hi 16KB + lo 16KB), ONE sync/stage.
// B fragments loaded directly from gmem (L2-resident, coalesced 256B/warp) with
// kb-level double-register prefetch. SInfo cached in smem.
#define ABUF 32768
#define SINF 98304
#define MAIN_SMEM (98304 + 36864 + 1024)

__launch_bounds__(256, 1)
__global__ void gemm_main_mma(int layer) {
    extern __shared__ unsigned char dsm[];
    uint32_t raw = smem_u32(dsm);
    uint32_t sb  = (raw + 1023u) & ~1023u;
    unsigned char* smp = dsm + (sb - raw);

    int tid  = threadIdx.x;
    int wid  = tid >> 5, lane = tid & 31;
    int wm   = wid & 1;                          // M warp (0..1) -> 64 rows
    int wn   = wid >> 1;                         // N warp (0..3) -> 64 cols
    int bm   = blockIdx.x;                       // 144 M tiles of 128 px

    const float* in   = layer ? g_h1T : g_xT;
    float*       outF = layer ? g_h2T : g_h1T;
    const uint2* __restrict__ bwh = g_bwmh + (size_t)layer*36*4096;
    const uint2* __restrict__ bwl = g_bwml + (size_t)layer*36*4096;

    int c4 = tid & 15;                           // channel quad (16 x 4 = 64 ch)
    int pg = tid >> 4;                           // pixel group (16 x 8 = 128 px)
    int b  = (bm*128) / HW;
    const float* inb = in + (size_t)b*HW*CH;

    // preload SInfo tile
    SInfo* sinfo_s = (SInfo*)(smp + SINF);
    {
        const SInfo* sg = g_sinfo + (size_t)(bm*128)*KTAPS;
        for (int i = tid; i < 128*KTAPS; i += 256) sinfo_s[i] = sg[i];
    }
    __syncthreads();

    float acc[4][8][4];
    #pragma unroll
    for (int i = 0; i < 4; i++)
        #pragma unroll
        for (int j = 0; j < 8; j++)
            #pragma unroll
            for (int k = 0; k < 4; k++) acc[i][j][k] = 0.0f;

    uint32_t a_rel = (uint32_t)((wm*64 + (lane & 15))*128 + (lane >> 4)*16);

    // gather + split + store stage S into buffer BUFID
    #define GATHER_STS(S, BUFID) do {                                                \
        int _tap = (S) % 9, _g = (S) / 9;                                            \
        int _cc  = _g*64 + c4*4;                                                     \
        unsigned char* _bp = smp + (BUFID)*ABUF;                                     \
        _Pragma("unroll")                                                            \
        for (int _i = 0; _i < 8; _i++) {                                             \
            int _px = pg*8 + _i;                                                     \
            SInfo _s = sinfo_s[_px*KTAPS + _tap];                                    \
            float4 _a0 = *(const float4*)(inb + (size_t)_s.i0*CH + _cc);             \
            float4 _a1 = *(const float4*)(inb + (size_t)_s.i1*CH + _cc);             \
            float4 _a2 = *(const float4*)(inb + (size_t)_s.i2*CH + _cc);             \
            float4 _a3 = *(const float4*)(inb + (size_t)_s.i3*CH + _cc);             \
            float _v0 = _s.w0*_a0.x + _s.w1*_a1.x + _s.w2*_a2.x + _s.w3*_a3.x;       \
            float _v1 = _s.w0*_a0.y + _s.w1*_a1.y + _s.w2*_a2.y + _s.w3*_a3.y;       \
            float _v2 = _s.w0*_a0.z + _s.w1*_a1.z + _s.w2*_a2.z + _s.w3*_a3.z;       \
            float _v3 = _s.w0*_a0.w + _s.w1*_a1.w + _s.w2*_a2.w + _s.w3*_a3.w;       \
            uint16_t _h0,_l0,_h1,_l1,_h2,_l2,_h3,_l3;                                \
            split_bf16(_v0,_h0,_l0); split_bf16(_v1,_h1,_l1);                        \
            split_bf16(_v2,_h2,_l2); split_bf16(_v3,_h3,_l3);                        \
            uint32_t _so = SW128((uint32_t)(_px*128 + c4*8));                        \
            *(uint2*)(_bp + _so) =                                                   \
                make_uint2((uint32_t)_h0 | ((uint32_t)_h1 << 16),                    \
                           (uint32_t)_h2 | ((uint32_t)_h3 << 16));                   \
            *(uint2*)(_bp + 16384 + _so) =                                           \
                make_uint2((uint32_t)_l0 | ((uint32_t)_l1 << 16),                    \
                           (uint32_t)_l2 | ((uint32_t)_l3 << 16));                   \
        }                                                                            \
    } while (0)

    uint2 bh[2][8], bl[2][8];

    // prologue: stage 0 into buf 0; prefetch B(stage0, kb0) into set 0
    GATHER_STS(0, 0);
    #pragma unroll
    for (int nb = 0; nb < 8; nb++) {
        size_t bi = (size_t)((0*32 + wn*8 + nb)*32 + lane);   // blk 0, kb 0
        bh[0][nb] = bwh[bi];
        bl[0][nb] = bwl[bi];
    }
    __syncthreads();

    #pragma unroll 1
    for (int s = 0; s < 36; s++) {
        int blk  = (s % 9)*4 + (s / 9);
        int nblk = (s < 35) ? (((s+1) % 9)*4 + ((s+1) / 9)) : blk;

        if (s + 1 < 36) GATHER_STS(s + 1, (s + 1) % 3);
        __syncthreads();

        uint32_t abase = sb + (uint32_t)(s % 3)*ABUF;
        #pragma unroll
        for (int kb = 0; kb < 4; kb++) {
            int cur = kb & 1, nxt = cur ^ 1;
            int pblk = (kb < 3) ? blk : nblk;
            int pkb  = (kb < 3) ? kb + 1 : 0;
            #pragma unroll
            for (int nb = 0; nb < 8; nb++) {
                size_t bi = (size_t)pblk*4096 + (size_t)((pkb*32 + wn*8 + nb)*32 + lane);
                bh[nxt][nb] = bwh[bi];
                bl[nxt][nb] = bwl[bi];
            }
            #pragma unroll
            for (int mi = 0; mi < 4; mi++) {
                uint32_t aoff = SW128(a_rel + (uint32_t)(mi*2048 + kb*32));
                uint32_t ah0,ah1,ah2,ah3, al0,al1,al2,al3;
                LDSM4(ah0,ah1,ah2,ah3, abase + aoff);
                LDSM4(al0,al1,al2,al3, abase + 16384 + aoff);
                #pragma unroll
                for (int nb = 0; nb < 8; nb++) {
                    MMA16816(acc[mi][nb], ah0,ah1,ah2,ah3, bh[cur][nb].x, bh[cur][nb].y);
                    MMA16816(acc[mi][nb], al0,al1,al2,al3, bh[cur][nb].x, bh[cur][nb].y);
                    MMA16816(acc[mi][nb], ah0,ah1,ah2,ah3, bl[cur][nb].x, bl[cur][nb].y);
                }
            }
        }
    }
    #undef GATHER_STS

    // ---- epilogue: ReLU, fp32 NHWC ----
    int crow = lane >> 2, ccol = (lane & 3)*2;
    #pragma unroll
    for (int mi = 0; mi < 4; mi++) {
        int px0 = bm*128 + wm*64 + mi*16;
        #pragma unroll
        for (int nb = 0; nb < 8; nb++) {
            int n = wn*64 + nb*8 + ccol;
            float* o0 = outF + (size_t)(px0 + crow    )*OUTC + n;
            float* o1 = outF + (size_t)(px0 + crow + 8)*OUTC + n;
            *(float2*)o0 = make_float2(fmaxf(acc[mi][nb][0], 0.f), fmaxf(acc[mi][nb][1], 0.f));
            *(float2*)o1 = make_float2(fmaxf(acc[mi][nb][2], 0.f), fmaxf(acc[mi][nb][3], 0.f));
        }
    }
}

// ====================== launch ======================
extern "C" void kernel_launch(void* const* d_in, const int* in_sizes, int n_in,
                              void* d_out, int out_size) {
    (void)in_sizes; (void)n_in; (void)out_size;
    const float* x      = (const float*)d_in[0];
    const float* w_off0 = (const float*)d_in[1];
    const float* b_off0 = (const float*)d_in[2];
    const float* w0     = (const float*)d_in[3];
    const float* w_off1 = (const float*)d_in[4];
    const float* b_off1 = (const float*)d_in[5];
    const float* w1     = (const float*)d_in[6];
    float* out = (float*)d_out;

    cudaFuncSetAttribute(gemm_main_mma, cudaFuncAttributeMaxDynamicSharedMemorySize, MAIN_SMEM);
    cudaFuncSetAttribute(gemm_off_mma,  cudaFuncAttributeMaxDynamicSharedMemorySize, OFF_SMEM);

    prep_off_mma <<<(36*512 + 255)/256, 256>>>(w_off0, 0);
    prep_off_mma <<<(36*512 + 255)/256, 256>>>(w_off1, 1);
    prep_main_mma<<<(36*4096 + 255)/256, 256>>>(w0, 0);
    prep_main_mma<<<(36*4096 + 255)/256, 256>>>(w1, 1);

    dim3 tb(32, 8);
    dim3 tg(HW/32, CH/32, BATCH);
    nchw_to_nhwc_k<<<tg, tb>>>(x);

    // layer 1 (coords fused into offset epilogue)
    gemm_off_mma <<<MROWS/64, 256, OFF_SMEM >>>(0, b_off0);
    gemm_main_mma<<<MROWS/128, 256, MAIN_SMEM>>>(0);

    // layer 2
    gemm_off_mma <<<MROWS/64, 256, OFF_SMEM >>>(1, b_off1);
    gemm_main_mma<<<MROWS/128, 256, MAIN_SMEM>>>(1);

    nhwc_to_nchw_k<<<tg, tb>>>(out);
}

// round 14
// speedup vs baseline: 1.1899x; 1.1899x over previous
#include <cuda_runtime.h>
#include <cuda_bf16.h>
#include <stdint.h>
#include <math.h>

#define BATCH 2
#define CH    256
#define HH    96
#define WW    96
#define HW    (HH*WW)        // 9216
#define OUTC  256
#define KTAPS 9
#define KDIM  (KTAPS*CH)     // 2304
#define MROWS (BATCH*HW)     // 18432
#define NOFF  32             // 27 padded to 32

#define SW128(o) ((o) ^ ((((o) >> 3) & 0x70)))

struct __align__(16) SInfo { int i0,i1,i2,i3; float w0,w1,w2,w3; };

// ---- scratch (device globals: allocation-free) ----
__device__ float g_xT [MROWS*CH];        // x NHWC fp32
__device__ float g_h1T[MROWS*CH];        // layer-1 out NHWC fp32
__device__ float g_h2T[MROWS*CH];        // layer-2 out NHWC fp32
__device__ SInfo g_sinfo[MROWS*KTAPS];   // bilinear indices+weights
// main weights in mma-B-fragment order, bf16 hi/lo:
//   [layer][blk36 = tap*4+g][kb4][nb32][lane32] uint2{pack(k0,k1), pack(k0+8,k1+8)}
__device__ uint2 g_bwmh[2*36*4096];
__device__ uint2 g_bwml[2*36*4096];
// offset weights, same frag order, N=32: [layer][blk36][kb4][nb4][lane32]
__device__ uint2 g_bwoh[2*36*512];
__device__ uint2 g_bwol[2*36*512];

// ====================== helpers ======================
__device__ __forceinline__ uint32_t smem_u32(const void* p) {
    uint32_t a;
    asm("{ .reg .u64 t; cvta.to.shared.u64 t, %1; cvt.u32.u64 %0, t; }" : "=r"(a) : "l"(p));
    return a;
}

__device__ __forceinline__ void split_bf16(float v, uint16_t& h, uint16_t& l) {
    __nv_bfloat16 hb = __float2bfloat16_rn(v);
    float lo = v - __bfloat162float(hb);
    __nv_bfloat16 lb = __float2bfloat16_rn(lo);
    h = __bfloat16_as_ushort(hb);
    l = __bfloat16_as_ushort(lb);
}

#define LDSM4(r0,r1,r2,r3, addr)                                                    \
    asm volatile("ldmatrix.sync.aligned.m8n8.x4.shared.b16 {%0,%1,%2,%3}, [%4];"    \
        : "=r"(r0), "=r"(r1), "=r"(r2), "=r"(r3) : "r"(addr))

#define MMA16816(d, a0,a1,a2,a3, b0,b1)                                             \
    asm volatile("mma.sync.aligned.m16n8k16.row.col.f32.bf16.bf16.f32 "             \
        "{%0,%1,%2,%3}, {%4,%5,%6,%7}, {%8,%9}, {%0,%1,%2,%3};"                     \
        : "+f"((d)[0]), "+f"((d)[1]), "+f"((d)[2]), "+f"((d)[3])                    \
        : "r"(a0), "r"(a1), "r"(a2), "r"(a3), "r"(b0), "r"(b1))

#define CP_ASYNC16(dst, src) \
    asm volatile("cp.async.cg.shared.global [%0], [%1], 16;" :: "r"(dst), "l"(src))
#define CP_COMMIT() asm volatile("cp.async.commit_group;" ::: "memory")
#define CP_WAIT0()  asm volatile("cp.async.wait_group 0;" ::: "memory")

// ====================== weight prep ======================
__global__ void prep_main_mma(const float* __restrict__ w, int layer) {
    int idx = blockIdx.x*256 + threadIdx.x;           // 36*4096 = 147456
    if (idx >= 36*4096) return;
    int lane = idx & 31;
    int nb   = (idx >> 5) & 31;
    int kb   = (idx >> 10) & 3;
    int blk  = idx >> 12;
    int tap  = blk >> 2, g = blk & 3;
    int n    = nb*8 + (lane >> 2);
    int c0   = g*64 + kb*16 + (lane & 3)*2;
    const float* wb = w + (size_t)n*CH*KTAPS + tap;
    float v00 = wb[(size_t)(c0    )*KTAPS];
    float v01 = wb[(size_t)(c0 + 1)*KTAPS];
    float v10 = wb[(size_t)(c0 + 8)*KTAPS];
    float v11 = wb[(size_t)(c0 + 9)*KTAPS];
    uint16_t h00,l00,h01,l01,h10,l10,h11,l11;
    split_bf16(v00,h00,l00); split_bf16(v01,h01,l01);
    split_bf16(v10,h10,l10); split_bf16(v11,h11,l11);
    size_t o = (size_t)layer*36*4096 + idx;
    g_bwmh[o] = make_uint2((uint32_t)h00 | ((uint32_t)h01 << 16),
                           (uint32_t)h10 | ((uint32_t)h11 << 16));
    g_bwml[o] = make_uint2((uint32_t)l00 | ((uint32_t)l01 << 16),
                           (uint32_t)l10 | ((uint32_t)l11 << 16));
}

__global__ void prep_off_mma(const float* __restrict__ woff, int layer) {
    int idx = blockIdx.x*256 + threadIdx.x;           // 36*512 = 18432
    if (idx >= 36*512) return;
    int lane = idx & 31;
    int nb   = (idx >> 5) & 3;
    int kb   = (idx >> 7) & 3;
    int blk  = idx >> 9;
    int tap  = blk >> 2, g = blk & 3;
    int n    = nb*8 + (lane >> 2);
    int c0   = g*64 + kb*16 + (lane & 3)*2;
    float v00 = 0.f, v01 = 0.f, v10 = 0.f, v11 = 0.f;
    if (n < 27) {
        const float* wb = woff + (size_t)n*CH*KTAPS + tap;
        v00 = wb[(size_t)(c0    )*KTAPS];
        v01 = wb[(size_t)(c0 + 1)*KTAPS];
        v10 = wb[(size_t)(c0 + 8)*KTAPS];
        v11 = wb[(size_t)(c0 + 9)*KTAPS];
    }
    uint16_t h00,l00,h01,l01,h10,l10,h11,l11;
    split_bf16(v00,h00,l00); split_bf16(v01,h01,l01);
    split_bf16(v10,h10,l10); split_bf16(v11,h11,l11);
    size_t o = (size_t)layer*36*512 + idx;
    g_bwoh[o] = make_uint2((uint32_t)h00 | ((uint32_t)h01 << 16),
                           (uint32_t)h10 | ((uint32_t)h11 << 16));
    g_bwol[o] = make_uint2((uint32_t)l00 | ((uint32_t)l01 << 16),
                           (uint32_t)l10 | ((uint32_t)l11 << 16));
}

// ====================== layout transposes ======================
__global__ void nchw_to_nhwc_k(const float* __restrict__ src) {
    __shared__ float t[32][33];
    int b  = blockIdx.z;
    int p0 = blockIdx.x*32, c0 = blockIdx.y*32;
    int tx = threadIdx.x,  ty = threadIdx.y;
    #pragma unroll
    for (int i = 0; i < 32; i += 8)
        t[ty+i][tx] = src[(size_t)(b*CH + c0+ty+i)*HW + p0 + tx];
    __syncthreads();
    #pragma unroll
    for (int i = 0; i < 32; i += 8)
        g_xT[(size_t)(b*HW + p0+ty+i)*CH + c0 + tx] = t[tx][ty+i];
}

__global__ void nhwc_to_nchw_k(float* __restrict__ dst) {
    __shared__ float t[32][33];
    int b  = blockIdx.z;
    int p0 = blockIdx.x*32, c0 = blockIdx.y*32;
    int tx = threadIdx.x,  ty = threadIdx.y;
    #pragma unroll
    for (int i = 0; i < 32; i += 8)
        t[ty+i][tx] = g_h2T[(size_t)(b*HW + p0+ty+i)*CH + c0 + tx];
    __syncthreads();
    #pragma unroll
    for (int i = 0; i < 32; i += 8)
        dst[(size_t)(b*CH + c0+ty+i)*HW + p0 + tx] = t[tx][ty+i];
}

// ====================== offset conv (mma bf16x3, N=32, BM=64) + fused coords ======================
#define OA_H 0
#define OA_L 8192
#define OB_H 16384
#define OB_L 20480
#define OM_S 24576
#define OFF_SMEM (24576 + 8192 + 1024)

__launch_bounds__(256, 2)
__global__ void gemm_off_mma(int layer, const float* __restrict__ bias) {
    extern __shared__ unsigned char dsm[];
    uint32_t raw = smem_u32(dsm);
    uint32_t sb  = (raw + 1023u) & ~1023u;
    unsigned char* smp = dsm + (sb - raw);

    int tid = threadIdx.x, wid = tid >> 5, lane = tid & 31;
    int wm  = wid & 3, wn = wid >> 2;
    int bm  = blockIdx.x;                   // 288 tiles of 64 px
    const float* in = layer ? g_h1T : g_xT;
    const uint2* bwh = g_bwoh + (size_t)layer*36*512;
    const uint2* bwl = g_bwol + (size_t)layer*36*512;

    int c4 = tid & 15;                      // 4-ch quad within 64-ch group
    int pg = tid >> 4;                      // 4-px group
    int b  = (bm*64) / HW;
    int pbase = bm*64 - b*HW;
    const float* inb = in + (size_t)b*HW*CH;

    float acc[2][4];
    #pragma unroll
    for (int i = 0; i < 2; i++)
        #pragma unroll
        for (int j = 0; j < 4; j++) acc[i][j] = 0.0f;

    uint32_t a_rel = (uint32_t)((wm*16 + (lane & 15))*128 + (lane >> 4)*16);

    for (int g = 0; g < 4; g++) {
        #pragma unroll 1
        for (int tap = 0; tap < 9; tap++) {
            int blk = tap*4 + g;
            int cc  = g*64 + c4*4;
            int dy  = tap/3 - 1, dx = tap%3 - 1;
            float4 av[4];
            #pragma unroll
            for (int i = 0; i < 4; i++) {
                int px = pg*4 + i;
                int p  = pbase + px;
                int y  = p / WW, x = p - y*WW;
                int ny = y + dy, nx = x + dx;
                bool valid = ((unsigned)ny < HH) & ((unsigned)nx < WW);
                av[i] = valid ? *(const float4*)(inb + (size_t)(ny*WW + nx)*CH + cc)
                              : make_float4(0.f,0.f,0.f,0.f);
            }
            __syncthreads();
            CP_ASYNC16(sb + OB_H + tid*16, (const void*)((const uint4*)(bwh + (size_t)blk*512) + tid));
            CP_ASYNC16(sb + OB_L + tid*16, (const void*)((const uint4*)(bwl + (size_t)blk*512) + tid));
            CP_COMMIT();
            #pragma unroll
            for (int i = 0; i < 4; i++) {
                int px = pg*4 + i;
                uint16_t h0,l0,h1,l1,h2,l2,h3,l3;
                split_bf16(av[i].x,h0,l0); split_bf16(av[i].y,h1,l1);
                split_bf16(av[i].z,h2,l2); split_bf16(av[i].w,h3,l3);
                uint32_t so = SW128((uint32_t)(px*128 + c4*8));
                *(uint2*)(smp + OA_H + so) =
                    make_uint2((uint32_t)h0 | ((uint32_t)h1 << 16),
                               (uint32_t)h2 | ((uint32_t)h3 << 16));
                *(uint2*)(smp + OA_L + so) =
                    make_uint2((uint32_t)l0 | ((uint32_t)l1 << 16),
                               (uint32_t)l2 | ((uint32_t)l3 << 16));
            }
            CP_WAIT0();
            __syncthreads();

            #pragma unroll
            for (int kb = 0; kb < 4; kb++) {
                uint32_t aoff = SW128(a_rel + (uint32_t)(kb*32));
                uint32_t ah0,ah1,ah2,ah3, al0,al1,al2,al3;
                LDSM4(ah0,ah1,ah2,ah3, sb + OA_H + aoff);
                LDSM4(al0,al1,al2,al3, sb + OA_L + aoff);
                #pragma unroll
                for (int j = 0; j < 2; j++) {
                    int nb = wn*2 + j;
                    uint32_t boff = (uint32_t)(((kb*4 + nb)*32 + lane)*8);
                    uint2 bh = *(const uint2*)(smp + OB_H + boff);
                    uint2 bl = *(const uint2*)(smp + OB_L + boff);
                    MMA16816(acc[j], ah0,ah1,ah2,ah3, bh.x, bh.y);
                    MMA16816(acc[j], al0,al1,al2,al3, bh.x, bh.y);
                    MMA16816(acc[j], ah0,ah1,ah2,ah3, bl.x, bl.y);
                }
            }
        }
    }

    // ---- fused epilogue: om -> smem, then coords -> g_sinfo ----
    float* om_s = (float*)(smp + OM_S);
    int crow = lane >> 2, ccol = (lane & 3)*2;
    int prow = wm*16 + crow;
    #pragma unroll
    for (int j = 0; j < 2; j++) {
        int col = (wn*2 + j)*8 + ccol;
        float bv0 = (col     < 27) ? __ldg(bias + col)     : 0.0f;
        float bv1 = (col + 1 < 27) ? __ldg(bias + col + 1) : 0.0f;
        om_s[prow*32 + col]       = acc[j][0] + bv0;
        om_s[prow*32 + col + 1]   = acc[j][1] + bv1;
        om_s[(prow+8)*32 + col]   = acc[j][2] + bv0;
        om_s[(prow+8)*32 + col+1] = acc[j][3] + bv1;
    }
    __syncthreads();

    #pragma unroll
    for (int t = 0; t < 3; t++) {
        int i = tid + t*256;
        if (i < 64*KTAPS) {
            int px  = i / 9;
            int tap = i - px*9;
            int gp  = bm*64 + px;
            int p   = gp - b*HW;
            int y   = p / WW, x = p - y*WW;
            const float* om = om_s + px*32;
            float ody = om[2*tap], odx = om[2*tap + 1];
            float m   = 1.0f / (1.0f + expf(-om[18 + tap]));
            float ys = (float)(y + tap/3 - 1) + ody;
            float xs = (float)(x + tap%3 - 1) + odx;
            float fy0 = floorf(ys), fx0 = floorf(xs);
            int y0 = (int)fy0, x0 = (int)fx0;
            int y1 = y0 + 1,   x1 = x0 + 1;
            float wy1 = ys - fy0, wx1 = xs - fx0;
            float wy0 = 1.0f - wy1, wx0 = 1.0f - wx1;
            int y0c = min(max(y0,0),HH-1), y1c = min(max(y1,0),HH-1);
            int x0c = min(max(x0,0),WW-1), x1c = min(max(x1,0),WW-1);
            float vy0 = ((unsigned)y0 < HH) ? 1.0f : 0.0f;
            float vy1 = ((unsigned)y1 < HH) ? 1.0f : 0.0f;
            float vx0 = ((unsigned)x0 < WW) ? 1.0f : 0.0f;
            float vx1 = ((unsigned)x1 < WW) ? 1.0f : 0.0f;
            SInfo s;
            s.i0 = y0c*WW + x0c;  s.w0 = wy0*wx0*m*vy0*vx0;
            s.i1 = y0c*WW + x1c;  s.w1 = wy0*wx1*m*vy0*vx1;
            s.i2 = y1c*WW + x0c;  s.w2 = wy1*wx0*m*vy1*vx0;
            s.i3 = y1c*WW + x1c;  s.w3 = wy1*wx1*m*vy1*vx1;
            g_sinfo[(size_t)gp*KTAPS + tap] = s;
        }
    }
}

// ====================== main deformable conv: mma.sync bf16x3, BM=64 BN=256 ======================
// EXACT R12 structure (best known): 2 CTAs/SM for cross-CTA phase overlap.
// SMEM: A hi/lo 2x8KB, B hi/lo 2x32KB, SInfo 64*9*32B = 18432B -> ~100KB.
#define SA_H 0
#define SA_L 8192
#define SB_H 16384
#define SB_L 49152
#define SINF 81920
#define MAIN_SMEM (81920 + 18432 + 1024)

__launch_bounds__(256, 2)
__global__ void gemm_main_mma(int layer) {
    extern __shared__ unsigned char dsm[];
    uint32_t raw = smem_u32(dsm);
    uint32_t sb  = (raw + 1023u) & ~1023u;
    unsigned char* smp = dsm + (sb - raw);

    int tid  = threadIdx.x;
    int wid  = tid >> 5, lane = tid & 31;
    int wm   = wid & 1;                          // M warp (0..1) -> 32 rows
    int wn   = wid >> 1;                         // N warp (0..3) -> 64 cols
    int bm   = blockIdx.x;                       // 288 M tiles of 64 px

    const float* in   = layer ? g_h1T : g_xT;
    float*       outF = layer ? g_h2T : g_h1T;
    const uint2* bwh  = g_bwmh + (size_t)layer*36*4096;
    const uint2* bwl  = g_bwml + (size_t)layer*36*4096;

    int c4 = tid & 15;                           // channel quad (16 x 4 = 64 ch)
    int pg = tid >> 4;                           // pixel group (16 x 4 = 64 px)
    int b  = (bm*64) / HW;
    const float* inb = in + (size_t)b*HW*CH;

    // preload SInfo for this tile into smem (reused by all 4 channel groups)
    SInfo* sinfo_s = (SInfo*)(smp + SINF);
    {
        const SInfo* sg = g_sinfo + (size_t)(bm*64)*KTAPS;
        for (int i = tid; i < 64*KTAPS; i += 256) sinfo_s[i] = sg[i];
    }
    __syncthreads();

    float acc[2][8][4];
    #pragma unroll
    for (int i = 0; i < 2; i++)
        #pragma unroll
        for (int j = 0; j < 8; j++)
            #pragma unroll
            for (int k = 0; k < 4; k++) acc[i][j][k] = 0.0f;

    uint32_t a_rel = (uint32_t)((wm*32 + (lane & 15))*128 + (lane >> 4)*16);

    for (int g = 0; g < 4; g++) {
        #pragma unroll 1
        for (int tap = 0; tap < 9; tap++) {
            int blk = tap*4 + g;
            int cc  = g*64 + c4*4;
            // ---- gather + blend into regs (4 px x 4 ch) ----
            float v[16];
            #pragma unroll
            for (int i = 0; i < 4; i++) {
                int px = pg*4 + i;
                SInfo s = sinfo_s[px*KTAPS + tap];
                float4 a0 = *(const float4*)(inb + (size_t)s.i0*CH + cc);
                float4 a1 = *(const float4*)(inb + (size_t)s.i1*CH + cc);
                float4 a2 = *(const float4*)(inb + (size_t)s.i2*CH + cc);
                float4 a3 = *(const float4*)(inb + (size_t)s.i3*CH + cc);
                v[i*4+0] = s.w0*a0.x + s.w1*a1.x + s.w2*a2.x + s.w3*a3.x;
                v[i*4+1] = s.w0*a0.y + s.w1*a1.y + s.w2*a2.y + s.w3*a3.y;
                v[i*4+2] = s.w0*a0.z + s.w1*a1.z + s.w2*a2.z + s.w3*a3.z;
                v[i*4+3] = s.w0*a0.w + s.w1*a1.w + s.w2*a2.w + s.w3*a3.w;
            }
            __syncthreads();
            // ---- B via cp.async (32KB per split, 8 uint4 per thread per split) ----
            {
                const uint4* sH = (const uint4*)(bwh + (size_t)blk*4096);
                const uint4* sL = (const uint4*)(bwl + (size_t)blk*4096);
                #pragma unroll
                for (int it = 0; it < 8; it++) {
                    uint32_t u = tid + it*256;
                    CP_ASYNC16(sb + SB_H + u*16, (const void*)(sH + u));
                    CP_ASYNC16(sb + SB_L + u*16, (const void*)(sL + u));
                }
                CP_COMMIT();
            }
            // ---- A split + store ----
            #pragma unroll
            for (int i = 0; i < 4; i++) {
                int px = pg*4 + i;
                uint16_t h0,l0,h1,l1,h2,l2,h3,l3;
                split_bf16(v[i*4+0],h0,l0); split_bf16(v[i*4+1],h1,l1);
                split_bf16(v[i*4+2],h2,l2); split_bf16(v[i*4+3],h3,l3);
                uint32_t so = SW128((uint32_t)(px*128 + c4*8));
                *(uint2*)(smp + SA_H + so) =
                    make_uint2((uint32_t)h0 | ((uint32_t)h1 << 16),
                               (uint32_t)h2 | ((uint32_t)h3 << 16));
                *(uint2*)(smp + SA_L + so) =
                    make_uint2((uint32_t)l0 | ((uint32_t)l1 << 16),
                               (uint32_t)l2 | ((uint32_t)l3 << 16));
            }
            CP_WAIT0();
            __syncthreads();

            // ---- compute: 4 k16 steps x 2 m16 x 8 n8 x 3 splits ----
            #pragma unroll
            for (int kb = 0; kb < 4; kb++) {
                uint2 bh[8], bl[8];
                #pragma unroll
                for (int nb = 0; nb < 8; nb++) {
                    uint32_t boff = (uint32_t)(((kb*32 + wn*8 + nb)*32 + lane)*8);
                    bh[nb] = *(const uint2*)(smp + SB_H + boff);
                    bl[nb] = *(const uint2*)(smp + SB_L + boff);
                }
                #pragma unroll
                for (int mi = 0; mi < 2; mi++) {
                    uint32_t aoff = SW128(a_rel + (uint32_t)(mi*2048 + kb*32));
                    uint32_t ah0,ah1,ah2,ah3, al0,al1,al2,al3;
                    LDSM4(ah0,ah1,ah2,ah3, sb + SA_H + aoff);
                    LDSM4(al0,al1,al2,al3, sb + SA_L + aoff);
                    #pragma unroll
                    for (int nb = 0; nb < 8; nb++) {
                        MMA16816(acc[mi][nb], ah0,ah1,ah2,ah3, bh[nb].x, bh[nb].y);
                        MMA16816(acc[mi][nb], al0,al1,al2,al3, bh[nb].x, bh[nb].y);
                        MMA16816(acc[mi][nb], ah0,ah1,ah2,ah3, bl[nb].x, bl[nb].y);
                    }
                }
            }
        }
    }

    // ---- epilogue: ReLU, fp32 NHWC ----
    int crow = lane >> 2, ccol = (lane & 3)*2;
    #pragma unroll
    for (int mi = 0; mi < 2; mi++) {
        int px0 = bm*64 + wm*32 + mi*16;
        #pragma unroll
        for (int nb = 0; nb < 8; nb++) {
            int n = wn*64 + nb*8 + ccol;
            float* o0 = outF + (size_t)(px0 + crow    )*OUTC + n;
            float* o1 = outF + (size_t)(px0 + crow + 8)*OUTC + n;
            *(float2*)o0 = make_float2(fmaxf(acc[mi][nb][0], 0.f), fmaxf(acc[mi][nb][1], 0.f));
            *(float2*)o1 = make_float2(fmaxf(acc[mi][nb][2], 0.f), fmaxf(acc[mi][nb][3], 0.f));
        }
    }
}

// ====================== launch ======================
extern "C" void kernel_launch(void* const* d_in, const int* in_sizes, int n_in,
                              void* d_out, int out_size) {
    (void)in_sizes; (void)n_in; (void)out_size;
    const float* x      = (const float*)d_in[0];
    const float* w_off0 = (const float*)d_in[1];
    const float* b_off0 = (const float*)d_in[2];
    const float* w0     = (const float*)d_in[3];
    const float* w_off1 = (const float*)d_in[4];
    const float* b_off1 = (const float*)d_in[5];
    const float* w1     = (const float*)d_in[6];
    float* out = (float*)d_out;

    cudaFuncSetAttribute(gemm_main_mma, cudaFuncAttributeMaxDynamicSharedMemorySize, MAIN_SMEM);
    cudaFuncSetAttribute(gemm_off_mma,  cudaFuncAttributeMaxDynamicSharedMemorySize, OFF_SMEM);

    prep_off_mma <<<(36*512 + 255)/256, 256>>>(w_off0, 0);
    prep_off_mma <<<(36*512 + 255)/256, 256>>>(w_off1, 1);
    prep_main_mma<<<(36*4096 + 255)/256, 256>>>(w0, 0);
    prep_main_mma<<<(36*4096 + 255)/256, 256>>>(w1, 1);

    dim3 tb(32, 8);
    dim3 tg(HW/32, CH/32, BATCH);
    nchw_to_nhwc_k<<<tg, tb>>>(x);

    // layer 1 (coords fused into offset epilogue)
    gemm_off_mma <<<MROWS/64, 256, OFF_SMEM >>>(0, b_off0);
    gemm_main_mma<<<MROWS/64, 256, MAIN_SMEM>>>(0);

    // layer 2
    gemm_off_mma <<<MROWS/64, 256, OFF_SMEM >>>(1, b_off1);
    gemm_main_mma<<<MROWS/64, 256, MAIN_SMEM>>>(1);

    nhwc_to_nchw_k<<<tg, tb>>>(out);
}

// round 15
// speedup vs baseline: 1.2280x; 1.0320x over previous
#include <cuda_runtime.h>
#include <cuda_bf16.h>
#include <stdint.h>
#include <math.h>

#define BATCH 2
#define CH    256
#define HH    96
#define WW    96
#define HW    (HH*WW)        // 9216
#define OUTC  256
#define KTAPS 9
#define KDIM  (KTAPS*CH)     // 2304
#define MROWS (BATCH*HW)     // 18432
#define NOFF  32             // 27 padded to 32

#define SW128(o) ((o) ^ ((((o) >> 3) & 0x70)))

struct __align__(16) SInfo { int i0,i1,i2,i3; float w0,w1,w2,w3; };

// ---- scratch (device globals: allocation-free) ----
__device__ float g_xT [MROWS*CH];        // x NHWC fp32
__device__ float g_h1T[MROWS*CH];        // layer-1 out NHWC fp32
__device__ float g_h2T[MROWS*CH];        // layer-2 out NHWC fp32
__device__ SInfo g_sinfo[MROWS*KTAPS];   // bilinear indices+weights
// main weights, bf16 hi/lo, packed as ldmatrix-ready 8x8 b16 tiles:
//   layout (uint2 units): ((blk36*4 + kb)*16 + nbp)*64 + row*2 + half
//   each 512B unit = 4 matrices (m0: n=2nbp,k-lo | m1: n=2nbp,k-hi | m2: n=2nbp+1,k-lo | m3: k-hi)
__device__ uint2 g_bwmh[2*36*4096];
__device__ uint2 g_bwml[2*36*4096];
// offset weights, plain frag order, N=32: [layer][blk36][kb4][nb4][lane32]
__device__ uint2 g_bwoh[2*36*512];
__device__ uint2 g_bwol[2*36*512];

// ====================== helpers ======================
__device__ __forceinline__ uint32_t smem_u32(const void* p) {
    uint32_t a;
    asm("{ .reg .u64 t; cvta.to.shared.u64 t, %1; cvt.u32.u64 %0, t; }" : "=r"(a) : "l"(p));
    return a;
}

__device__ __forceinline__ void split_bf16(float v, uint16_t& h, uint16_t& l) {
    __nv_bfloat16 hb = __float2bfloat16_rn(v);
    float lo = v - __bfloat162float(hb);
    __nv_bfloat16 lb = __float2bfloat16_rn(lo);
    h = __bfloat16_as_ushort(hb);
    l = __bfloat16_as_ushort(lb);
}

#define LDSM4(r0,r1,r2,r3, addr)                                                    \
    asm volatile("ldmatrix.sync.aligned.m8n8.x4.shared.b16 {%0,%1,%2,%3}, [%4];"    \
        : "=r"(r0), "=r"(r1), "=r"(r2), "=r"(r3) : "r"(addr))

#define MMA16816(d, a0,a1,a2,a3, b0,b1)                                             \
    asm volatile("mma.sync.aligned.m16n8k16.row.col.f32.bf16.bf16.f32 "             \
        "{%0,%1,%2,%3}, {%4,%5,%6,%7}, {%8,%9}, {%0,%1,%2,%3};"                     \
        : "+f"((d)[0]), "+f"((d)[1]), "+f"((d)[2]), "+f"((d)[3])                    \
        : "r"(a0), "r"(a1), "r"(a2), "r"(a3), "r"(b0), "r"(b1))

#define CP_ASYNC16(dst, src) \
    asm volatile("cp.async.cg.shared.global [%0], [%1], 16;" :: "r"(dst), "l"(src))
#define CP_COMMIT() asm volatile("cp.async.commit_group;" ::: "memory")
#define CP_WAIT0()  asm volatile("cp.async.wait_group 0;" ::: "memory")

// ====================== combined weight prep (1 launch) ======================
// blocks [0,576): main layer0; [576,1152): main layer1;
// blocks [1152,1224): off layer0; [1224,1296): off layer1.
__global__ void prep_all(const float* __restrict__ w0, const float* __restrict__ w1,
                         const float* __restrict__ woff0, const float* __restrict__ woff1) {
    int bid = blockIdx.x;
    if (bid < 1152) {
        int layer = (bid >= 576) ? 1 : 0;
        const float* w = layer ? w1 : w0;
        int idx = (bid - layer*576)*256 + threadIdx.x;   // [0, 147456)
        // decode ldmatrix-unit layout
        int half = idx & 1;
        int row  = (idx >> 1) & 31;
        int nbp  = (idx >> 6) & 15;
        int kb   = (idx >> 10) & 3;
        int blk  = idx >> 12;                            // 0..35
        int tap  = blk >> 2, g = blk & 3;
        int m    = row >> 3, r = row & 7;
        int n    = (nbp*2 + (m >> 1))*8 + r;
        int kbase = g*64 + kb*16 + (m & 1)*8 + half*4;
        const float* wb = w + ((size_t)n*CH + kbase)*KTAPS + tap;
        float v0 = wb[0*KTAPS], v1 = wb[1*KTAPS], v2 = wb[2*KTAPS], v3 = wb[3*KTAPS];
        uint16_t h0,l0,h1,l1,h2,l2,h3,l3;
        split_bf16(v0,h0,l0); split_bf16(v1,h1,l1);
        split_bf16(v2,h2,l2); split_bf16(v3,h3,l3);
        size_t o = (size_t)layer*36*4096 + idx;
        g_bwmh[o] = make_uint2((uint32_t)h0 | ((uint32_t)h1 << 16),
                               (uint32_t)h2 | ((uint32_t)h3 << 16));
        g_bwml[o] = make_uint2((uint32_t)l0 | ((uint32_t)l1 << 16),
                               (uint32_t)l2 | ((uint32_t)l3 << 16));
    } else {
        int bb = bid - 1152;
        int layer = (bb >= 72) ? 1 : 0;
        const float* woff = layer ? woff1 : woff0;
        int idx = (bb - layer*72)*256 + threadIdx.x;     // [0, 18432)
        int lane = idx & 31;
        int nb   = (idx >> 5) & 3;
        int kb   = (idx >> 7) & 3;
        int blk  = idx >> 9;
        int tap  = blk >> 2, g = blk & 3;
        int n    = nb*8 + (lane >> 2);
        int c0   = g*64 + kb*16 + (lane & 3)*2;
        float v00 = 0.f, v01 = 0.f, v10 = 0.f, v11 = 0.f;
        if (n < 27) {
            const float* wb = woff + (size_t)n*CH*KTAPS + tap;
            v00 = wb[(size_t)(c0    )*KTAPS];
            v01 = wb[(size_t)(c0 + 1)*KTAPS];
            v10 = wb[(size_t)(c0 + 8)*KTAPS];
            v11 = wb[(size_t)(c0 + 9)*KTAPS];
        }
        uint16_t h00,l00,h01,l01,h10,l10,h11,l11;
        split_bf16(v00,h00,l00); split_bf16(v01,h01,l01);
        split_bf16(v10,h10,l10); split_bf16(v11,h11,l11);
        size_t o = (size_t)layer*36*512 + idx;
        g_bwoh[o] = make_uint2((uint32_t)h00 | ((uint32_t)h01 << 16),
                               (uint32_t)h10 | ((uint32_t)h11 << 16));
        g_bwol[o] = make_uint2((uint32_t)l00 | ((uint32_t)l01 << 16),
                               (uint32_t)l10 | ((uint32_t)l11 << 16));
    }
}

// ====================== layout transposes ======================
__global__ void nchw_to_nhwc_k(const float* __restrict__ src) {
    __shared__ float t[32][33];
    int b  = blockIdx.z;
    int p0 = blockIdx.x*32, c0 = blockIdx.y*32;
    int tx = threadIdx.x,  ty = threadIdx.y;
    #pragma unroll
    for (int i = 0; i < 32; i += 8)
        t[ty+i][tx] = src[(size_t)(b*CH + c0+ty+i)*HW + p0 + tx];
    __syncthreads();
    #pragma unroll
    for (int i = 0; i < 32; i += 8)
        g_xT[(size_t)(b*HW + p0+ty+i)*CH + c0 + tx] = t[tx][ty+i];
}

__global__ void nhwc_to_nchw_k(float* __restrict__ dst) {
    __shared__ float t[32][33];
    int b  = blockIdx.z;
    int p0 = blockIdx.x*32, c0 = blockIdx.y*32;
    int tx = threadIdx.x,  ty = threadIdx.y;
    #pragma unroll
    for (int i = 0; i < 32; i += 8)
        t[ty+i][tx] = g_h2T[(size_t)(b*HW + p0+ty+i)*CH + c0 + tx];
    __syncthreads();
    #pragma unroll
    for (int i = 0; i < 32; i += 8)
        dst[(size_t)(b*CH + c0+ty+i)*HW + p0 + tx] = t[tx][ty+i];
}

// ====================== offset conv (mma bf16x3, N=32, BM=64) + fused coords ======================
#define OA_H 0
#define OA_L 8192
#define OB_H 16384
#define OB_L 20480
#define OM_S 24576
#define OFF_SMEM (24576 + 8192 + 1024)

__launch_bounds__(256, 2)
__global__ void gemm_off_mma(int layer, const float* __restrict__ bias) {
    extern __shared__ unsigned char dsm[];
    uint32_t raw = smem_u32(dsm);
    uint32_t sb  = (raw + 1023u) & ~1023u;
    unsigned char* smp = dsm + (sb - raw);

    int tid = threadIdx.x, wid = tid >> 5, lane = tid & 31;
    int wm  = wid & 3, wn = wid >> 2;
    int bm  = blockIdx.x;                   // 288 tiles of 64 px
    const float* in = layer ? g_h1T : g_xT;
    const uint2* bwh = g_bwoh + (size_t)layer*36*512;
    const uint2* bwl = g_bwol + (size_t)layer*36*512;

    int c4 = tid & 15;                      // 4-ch quad within 64-ch group
    int pg = tid >> 4;                      // 4-px group
    int b  = (bm*64) / HW;
    int pbase = bm*64 - b*HW;
    const float* inb = in + (size_t)b*HW*CH;

    float acc[2][4];
    #pragma unroll
    for (int i = 0; i < 2; i++)
        #pragma unroll
        for (int j = 0; j < 4; j++) acc[i][j] = 0.0f;

    uint32_t a_rel = (uint32_t)((wm*16 + (lane & 15))*128 + (lane >> 4)*16);

    for (int g = 0; g < 4; g++) {
        #pragma unroll 1
        for (int tap = 0; tap < 9; tap++) {
            int blk = tap*4 + g;
            int cc  = g*64 + c4*4;
            int dy  = tap/3 - 1, dx = tap%3 - 1;
            float4 av[4];
            #pragma unroll
            for (int i = 0; i < 4; i++) {
                int px = pg*4 + i;
                int p  = pbase + px;
                int y  = p / WW, x = p - y*WW;
                int ny = y + dy, nx = x + dx;
                bool valid = ((unsigned)ny < HH) & ((unsigned)nx < WW);
                av[i] = valid ? *(const float4*)(inb + (size_t)(ny*WW + nx)*CH + cc)
                              : make_float4(0.f,0.f,0.f,0.f);
            }
            __syncthreads();
            CP_ASYNC16(sb + OB_H + tid*16, (const void*)((const uint4*)(bwh + (size_t)blk*512) + tid));
            CP_ASYNC16(sb + OB_L + tid*16, (const void*)((const uint4*)(bwl + (size_t)blk*512) + tid));
            CP_COMMIT();
            #pragma unroll
            for (int i = 0; i < 4; i++) {
                int px = pg*4 + i;
                uint16_t h0,l0,h1,l1,h2,l2,h3,l3;
                split_bf16(av[i].x,h0,l0); split_bf16(av[i].y,h1,l1);
                split_bf16(av[i].z,h2,l2); split_bf16(av[i].w,h3,l3);
                uint32_t so = SW128((uint32_t)(px*128 + c4*8));
                *(uint2*)(smp + OA_H + so) =
                    make_uint2((uint32_t)h0 | ((uint32_t)h1 << 16),
                               (uint32_t)h2 | ((uint32_t)h3 << 16));
                *(uint2*)(smp + OA_L + so) =
                    make_uint2((uint32_t)l0 | ((uint32_t)l1 << 16),
                               (uint32_t)l2 | ((uint32_t)l3 << 16));
            }
            CP_WAIT0();
            __syncthreads();

            #pragma unroll
            for (int kb = 0; kb < 4; kb++) {
                uint32_t aoff = SW128(a_rel + (uint32_t)(kb*32));
                uint32_t ah0,ah1,ah2,ah3, al0,al1,al2,al3;
                LDSM4(ah0,ah1,ah2,ah3, sb + OA_H + aoff);
                LDSM4(al0,al1,al2,al3, sb + OA_L + aoff);
                #pragma unroll
                for (int j = 0; j < 2; j++) {
                    int nb = wn*2 + j;
                    uint32_t boff = (uint32_t)(((kb*4 + nb)*32 + lane)*8);
                    uint2 bh = *(const uint2*)(smp + OB_H + boff);
                    uint2 bl = *(const uint2*)(smp + OB_L + boff);
                    MMA16816(acc[j], ah0,ah1,ah2,ah3, bh.x, bh.y);
                    MMA16816(acc[j], al0,al1,al2,al3, bh.x, bh.y);
                    MMA16816(acc[j], ah0,ah1,ah2,ah3, bl.x, bl.y);
                }
            }
        }
    }

    // ---- fused epilogue: om -> smem, then coords -> g_sinfo ----
    float* om_s = (float*)(smp + OM_S);
    int crow = lane >> 2, ccol = (lane & 3)*2;
    int prow = wm*16 + crow;
    #pragma unroll
    for (int j = 0; j < 2; j++) {
        int col = (wn*2 + j)*8 + ccol;
        float bv0 = (col     < 27) ? __ldg(bias + col)     : 0.0f;
        float bv1 = (col + 1 < 27) ? __ldg(bias + col + 1) : 0.0f;
        om_s[prow*32 + col]       = acc[j][0] + bv0;
        om_s[prow*32 + col + 1]   = acc[j][1] + bv1;
        om_s[(prow+8)*32 + col]   = acc[j][2] + bv0;
        om_s[(prow+8)*32 + col+1] = acc[j][3] + bv1;
    }
    __syncthreads();

    #pragma unroll
    for (int t = 0; t < 3; t++) {
        int i = tid + t*256;
        if (i < 64*KTAPS) {
            int px  = i / 9;
            int tap = i - px*9;
            int gp  = bm*64 + px;
            int p   = gp - b*HW;
            int y   = p / WW, x = p - y*WW;
            const float* om = om_s + px*32;
            float ody = om[2*tap], odx = om[2*tap + 1];
            float m   = 1.0f / (1.0f + expf(-om[18 + tap]));
            float ys = (float)(y + tap/3 - 1) + ody;
            float xs = (float)(x + tap%3 - 1) + odx;
            float fy0 = floorf(ys), fx0 = floorf(xs);
            int y0 = (int)fy0, x0 = (int)fx0;
            int y1 = y0 + 1,   x1 = x0 + 1;
            float wy1 = ys - fy0, wx1 = xs - fx0;
            float wy0 = 1.0f - wy1, wx0 = 1.0f - wx1;
            int y0c = min(max(y0,0),HH-1), y1c = min(max(y1,0),HH-1);
            int x0c = min(max(x0,0),WW-1), x1c = min(max(x1,0),WW-1);
            float vy0 = ((unsigned)y0 < HH) ? 1.0f : 0.0f;
            float vy1 = ((unsigned)y1 < HH) ? 1.0f : 0.0f;
            float vx0 = ((unsigned)x0 < WW) ? 1.0f : 0.0f;
            float vx1 = ((unsigned)x1 < WW) ? 1.0f : 0.0f;
            SInfo s;
            s.i0 = y0c*WW + x0c;  s.w0 = wy0*wx0*m*vy0*vx0;
            s.i1 = y0c*WW + x1c;  s.w1 = wy0*wx1*m*vy0*vx1;
            s.i2 = y1c*WW + x0c;  s.w2 = wy1*wx0*m*vy1*vx0;
            s.i3 = y1c*WW + x1c;  s.w3 = wy1*wx1*m*vy1*vx1;
            g_sinfo[(size_t)gp*KTAPS + tap] = s;
        }
    }
}

// ====================== main deformable conv: mma.sync bf16x3, BM=64 BN=256 ======================
// R12/R14 structure (2 CTAs/SM) + B fragments via ldmatrix.x4 (4x fewer B-load issues).
// SMEM: A hi/lo 2x8KB, B hi/lo 2x32KB, SInfo 64*9*32B = 18432B -> ~100KB.
#define SA_H 0
#define SA_L 8192
#define SB_H 16384
#define SB_L 49152
#define SINF 81920
#define MAIN_SMEM (81920 + 18432 + 1024)

__launch_bounds__(256, 2)
__global__ void gemm_main_mma(int layer) {
    extern __shared__ unsigned char dsm[];
    uint32_t raw = smem_u32(dsm);
    uint32_t sb  = (raw + 1023u) & ~1023u;
    unsigned char* smp = dsm + (sb - raw);

    int tid  = threadIdx.x;
    int wid  = tid >> 5, lane = tid & 31;
    int wm   = wid & 1;                          // M warp (0..1) -> 32 rows
    int wn   = wid >> 1;                         // N warp (0..3) -> 64 cols
    int bm   = blockIdx.x;                       // 288 M tiles of 64 px

    const float* in   = layer ? g_h1T : g_xT;
    float*       outF = layer ? g_h2T : g_h1T;
    const uint2* bwh  = g_bwmh + (size_t)layer*36*4096;
    const uint2* bwl  = g_bwml + (size_t)layer*36*4096;

    int c4 = tid & 15;                           // channel quad (16 x 4 = 64 ch)
    int pg = tid >> 4;                           // pixel group (16 x 4 = 64 px)
    int b  = (bm*64) / HW;
    const float* inb = in + (size_t)b*HW*CH;

    // preload SInfo for this tile into smem (reused by all 4 channel groups)
    SInfo* sinfo_s = (SInfo*)(smp + SINF);
    {
        const SInfo* sg = g_sinfo + (size_t)(bm*64)*KTAPS;
        for (int i = tid; i < 64*KTAPS; i += 256) sinfo_s[i] = sg[i];
    }
    __syncthreads();

    float acc[2][8][4];
    #pragma unroll
    for (int i = 0; i < 2; i++)
        #pragma unroll
        for (int j = 0; j < 8; j++)
            #pragma unroll
            for (int k = 0; k < 4; k++) acc[i][j][k] = 0.0f;

    uint32_t a_rel = (uint32_t)((wm*32 + (lane & 15))*128 + (lane >> 4)*16);
    uint32_t b_lane16 = (uint32_t)(lane*16);

    for (int g = 0; g < 4; g++) {
        #pragma unroll 1
        for (int tap = 0; tap < 9; tap++) {
            int blk = tap*4 + g;
            int cc  = g*64 + c4*4;
            // ---- gather + blend into regs (4 px x 4 ch) ----
            float v[16];
            #pragma unroll
            for (int i = 0; i < 4; i++) {
                int px = pg*4 + i;
                SInfo s = sinfo_s[px*KTAPS + tap];
                float4 a0 = *(const float4*)(inb + (size_t)s.i0*CH + cc);
                float4 a1 = *(const float4*)(inb + (size_t)s.i1*CH + cc);
                float4 a2 = *(const float4*)(inb + (size_t)s.i2*CH + cc);
                float4 a3 = *(const float4*)(inb + (size_t)s.i3*CH + cc);
                v[i*4+0] = s.w0*a0.x + s.w1*a1.x + s.w2*a2.x + s.w3*a3.x;
                v[i*4+1] = s.w0*a0.y + s.w1*a1.y + s.w2*a2.y + s.w3*a3.y;
                v[i*4+2] = s.w0*a0.z + s.w1*a1.z + s.w2*a2.z + s.w3*a3.z;
                v[i*4+3] = s.w0*a0.w + s.w1*a1.w + s.w2*a2.w + s.w3*a3.w;
            }
            __syncthreads();
            // ---- B via cp.async (32KB per split, 8 uint4 per thread per split) ----
            {
                const uint4* sH = (const uint4*)(bwh + (size_t)blk*4096);
                const uint4* sL = (const uint4*)(bwl + (size_t)blk*4096);
                #pragma unroll
                for (int it = 0; it < 8; it++) {
                    uint32_t u = tid + it*256;
                    CP_ASYNC16(sb + SB_H + u*16, (const void*)(sH + u));
                    CP_ASYNC16(sb + SB_L + u*16, (const void*)(sL + u));
                }
                CP_COMMIT();
            }
            // ---- A split + store ----
            #pragma unroll
            for (int i = 0; i < 4; i++) {
                int px = pg*4 + i;
                uint16_t h0,l0,h1,l1,h2,l2,h3,l3;
                split_bf16(v[i*4+0],h0,l0); split_bf16(v[i*4+1],h1,l1);
                split_bf16(v[i*4+2],h2,l2); split_bf16(v[i*4+3],h3,l3);
                uint32_t so = SW128((uint32_t)(px*128 + c4*8));
                *(uint2*)(smp + SA_H + so) =
                    make_uint2((uint32_t)h0 | ((uint32_t)h1 << 16),
                               (uint32_t)h2 | ((uint32_t)h3 << 16));
                *(uint2*)(smp + SA_L + so) =
                    make_uint2((uint32_t)l0 | ((uint32_t)l1 << 16),
                               (uint32_t)l2 | ((uint32_t)l3 << 16));
            }
            CP_WAIT0();
            __syncthreads();

            // ---- compute: 4 k16 steps x 2 m16 x 8 n8 x 3 splits; B via ldmatrix ----
            #pragma unroll
            for (int kb = 0; kb < 4; kb++) {
                uint2 bh[8], bl[8];
                #pragma unroll
                for (int p = 0; p < 4; p++) {
                    int nbp = wn*4 + p;
                    uint32_t ba = sb + SB_H + (uint32_t)((kb*16 + nbp)*512) + b_lane16;
                    uint32_t r0,r1,r2,r3;
                    LDSM4(r0,r1,r2,r3, ba);
                    bh[2*p]   = make_uint2(r0,r1);
                    bh[2*p+1] = make_uint2(r2,r3);
                    LDSM4(r0,r1,r2,r3, ba + (SB_L - SB_H));
                    bl[2*p]   = make_uint2(r0,r1);
                    bl[2*p+1] = make_uint2(r2,r3);
                }
                #pragma unroll
                for (int mi = 0; mi < 2; mi++) {
                    uint32_t aoff = SW128(a_rel + (uint32_t)(mi*2048 + kb*32));
                    uint32_t ah0,ah1,ah2,ah3, al0,al1,al2,al3;
                    LDSM4(ah0,ah1,ah2,ah3, sb + SA_H + aoff);
                    LDSM4(al0,al1,al2,al3, sb + SA_L + aoff);
                    #pragma unroll
                    for (int nb = 0; nb < 8; nb++) {
                        MMA16816(acc[mi][nb], ah0,ah1,ah2,ah3, bh[nb].x, bh[nb].y);
                        MMA16816(acc[mi][nb], al0,al1,al2,al3, bh[nb].x, bh[nb].y);
                        MMA16816(acc[mi][nb], ah0,ah1,ah2,ah3, bl[nb].x, bl[nb].y);
                    }
                }
            }
        }
    }

    // ---- epilogue: ReLU, fp32 NHWC ----
    int crow = lane >> 2, ccol = (lane & 3)*2;
    #pragma unroll
    for (int mi = 0; mi < 2; mi++) {
        int px0 = bm*64 + wm*32 + mi*16;
        #pragma unroll
        for (int nb = 0; nb < 8; nb++) {
            int n = wn*64 + nb*8 + ccol;
            float* o0 = outF + (size_t)(px0 + crow    )*OUTC + n;
            float* o1 = outF + (size_t)(px0 + crow + 8)*OUTC + n;
            *(float2*)o0 = make_float2(fmaxf(acc[mi][nb][0], 0.f), fmaxf(acc[mi][nb][1], 0.f));
            *(float2*)o1 = make_float2(fmaxf(acc[mi][nb][2], 0.f), fmaxf(acc[mi][nb][3], 0.f));
        }
    }
}

// ====================== launch ======================
extern "C" void kernel_launch(void* const* d_in, const int* in_sizes, int n_in,
                              void* d_out, int out_size) {
    (void)in_sizes; (void)n_in; (void)out_size;
    const float* x      = (const float*)d_in[0];
    const float* w_off0 = (const float*)d_in[1];
    const float* b_off0 = (const float*)d_in[2];
    const float* w0     = (const float*)d_in[3];
    const float* w_off1 = (const float*)d_in[4];
    const float* b_off1 = (const float*)d_in[5];
    const float* w1     = (const float*)d_in[6];
    float* out = (float*)d_out;

    cudaFuncSetAttribute(gemm_main_mma, cudaFuncAttributeMaxDynamicSharedMemorySize, MAIN_SMEM);
    cudaFuncSetAttribute(gemm_off_mma,  cudaFuncAttributeMaxDynamicSharedMemorySize, OFF_SMEM);

    prep_all<<<1296, 256>>>(w0, w1, w_off0, w_off1);

    dim3 tb(32, 8);
    dim3 tg(HW/32, CH/32, BATCH);
    nchw_to_nhwc_k<<<tg, tb>>>(x);

    // layer 1 (coords fused into offset epilogue)
    gemm_off_mma <<<MROWS/64, 256, OFF_SMEM >>>(0, b_off0);
    gemm_main_mma<<<MROWS/64, 256, MAIN_SMEM>>>(0);

    // layer 2
    gemm_off_mma <<<MROWS/64, 256, OFF_SMEM >>>(1, b_off1);
    gemm_main_mma<<<MROWS/64, 256, MAIN_SMEM>>>(1);

    nhwc_to_nchw_k<<<tg, tb>>>(out);
}